// round 3
// baseline (speedup 1.0000x reference)
#include <cuda_runtime.h>

#define BATCH 32
#define CCH   512
#define RCH   256
#define HWSZ  1024

// Scratch (device-global arrays: the sanctioned alloc-free workaround)
__device__ float g_fkey [BATCH * RCH * HWSZ];           // 32 MB  [b][r][n]
__device__ float g_fprod[BATCH * RCH * HWSZ];           // 32 MB  [b][r][m]
__device__ float g_fval [BATCH * CCH * HWSZ];           // 64 MB  [b][c][m]
__device__ float g_energy[(size_t)BATCH * HWSZ * HWSZ]; // 128 MB [b][n][m] (softmax in-place)

// ---------------------------------------------------------------------------
// Projection: out[b][o][n] = sum_c W[o][c] * x[b][c][n] + bias[o]
// Destination global selected at compile time (no cudaGetSymbolAddress on host).
// Tile 64x64, BK=16, 256 threads, 4x4 per thread.
// ---------------------------------------------------------------------------
template<int M, int WHICH>
__global__ __launch_bounds__(256)
void proj_kernel(const float* __restrict__ x,
                 const float* __restrict__ W,
                 const float* __restrict__ bias)
{
    float* out = (WHICH == 0) ? g_fkey : (WHICH == 1) ? g_fprod : g_fval;

    const int K = CCH;
    __shared__ float As[16][64];   // [k][m]
    __shared__ float Bs[16][64];   // [k][n]

    const int b  = blockIdx.z;
    const int m0 = blockIdx.y * 64;
    const int n0 = blockIdx.x * 64;
    const int tid = threadIdx.x;
    const int tx = tid & 15;       // n sub-tile
    const int ty = tid >> 4;       // m sub-tile

    const float* xb = x + b * (CCH * HWSZ);

    float acc[4][4] = {};

    for (int k0 = 0; k0 < K; k0 += 16) {
        // A load: W[m0 + tid/4][k0 + (tid%4)*4 ..] -> As[k][m] (transposed scatter)
        {
            const int m  = tid >> 2;
            const int kq = (tid & 3) * 4;
            float4 v = *reinterpret_cast<const float4*>(&W[(m0 + m) * K + k0 + kq]);
            As[kq + 0][m] = v.x; As[kq + 1][m] = v.y;
            As[kq + 2][m] = v.z; As[kq + 3][m] = v.w;
        }
        // B load: direct copy
        {
            const int kr = tid >> 4;
            const int nq = (tid & 15) * 4;
            *reinterpret_cast<float4*>(&Bs[kr][nq]) =
                *reinterpret_cast<const float4*>(&xb[(k0 + kr) * HWSZ + n0 + nq]);
        }
        __syncthreads();

        #pragma unroll
        for (int k = 0; k < 16; k++) {
            float a[4], bb[4];
            *reinterpret_cast<float4*>(a)  = *reinterpret_cast<const float4*>(&As[k][ty * 4]);
            *reinterpret_cast<float4*>(bb) = *reinterpret_cast<const float4*>(&Bs[k][tx * 4]);
            #pragma unroll
            for (int i = 0; i < 4; i++)
                #pragma unroll
                for (int j = 0; j < 4; j++)
                    acc[i][j] += a[i] * bb[j];
        }
        __syncthreads();
    }

    float* ob = out + b * (M * HWSZ);
    #pragma unroll
    for (int i = 0; i < 4; i++) {
        const float bi = bias[m0 + ty * 4 + i];
        float4 v = make_float4(acc[i][0] + bi, acc[i][1] + bi,
                               acc[i][2] + bi, acc[i][3] + bi);
        *reinterpret_cast<float4*>(&ob[(m0 + ty * 4 + i) * HWSZ + n0 + tx * 4]) = v;
    }
}

// ---------------------------------------------------------------------------
// Energy: E[b][n][m] = sum_r fkey[b][r][n] * fprod[b][r][m]
// TN GEMM: both operands read K-major -> direct smem copies, no transpose.
// ---------------------------------------------------------------------------
__global__ __launch_bounds__(256)
void energy_kernel()
{
    __shared__ float As[16][64];   // [r][n]
    __shared__ float Bs[16][64];   // [r][m]

    const int b  = blockIdx.z;
    const int n0 = blockIdx.y * 64;   // key pixel (output row)
    const int m0 = blockIdx.x * 64;   // prod pixel (output col)
    const int tid = threadIdx.x;
    const int tx = tid & 15;
    const int ty = tid >> 4;

    const float* Kb = g_fkey  + b * (RCH * HWSZ);
    const float* Pb = g_fprod + b * (RCH * HWSZ);

    float acc[4][4] = {};

    for (int k0 = 0; k0 < RCH; k0 += 16) {
        const int kr = tid >> 4;
        const int cq = (tid & 15) * 4;
        *reinterpret_cast<float4*>(&As[kr][cq]) =
            *reinterpret_cast<const float4*>(&Kb[(k0 + kr) * HWSZ + n0 + cq]);
        *reinterpret_cast<float4*>(&Bs[kr][cq]) =
            *reinterpret_cast<const float4*>(&Pb[(k0 + kr) * HWSZ + m0 + cq]);
        __syncthreads();

        #pragma unroll
        for (int k = 0; k < 16; k++) {
            float a[4], bb[4];
            *reinterpret_cast<float4*>(a)  = *reinterpret_cast<const float4*>(&As[k][ty * 4]);
            *reinterpret_cast<float4*>(bb) = *reinterpret_cast<const float4*>(&Bs[k][tx * 4]);
            #pragma unroll
            for (int i = 0; i < 4; i++)
                #pragma unroll
                for (int j = 0; j < 4; j++)
                    acc[i][j] += a[i] * bb[j];
        }
        __syncthreads();
    }

    float* Eb = g_energy + (size_t)b * HWSZ * HWSZ;
    #pragma unroll
    for (int i = 0; i < 4; i++) {
        *reinterpret_cast<float4*>(&Eb[(size_t)(n0 + ty * 4 + i) * HWSZ + m0 + tx * 4]) =
            *reinterpret_cast<float4*>(acc[i]);
    }
}

// ---------------------------------------------------------------------------
// Softmax over last axis (row length 1024), in place on g_energy.
// One block (256 threads) per row; 4 elements per thread.
// ---------------------------------------------------------------------------
__device__ __forceinline__ float block_reduce(float v, bool do_max)
{
    __shared__ float red[8];
    #pragma unroll
    for (int o = 16; o > 0; o >>= 1) {
        const float other = __shfl_xor_sync(0xffffffffu, v, o);
        v = do_max ? fmaxf(v, other) : (v + other);
    }
    const int wid = threadIdx.x >> 5;
    if ((threadIdx.x & 31) == 0) red[wid] = v;
    __syncthreads();
    float r = red[0];
    #pragma unroll
    for (int w = 1; w < 8; w++) r = do_max ? fmaxf(r, red[w]) : (r + red[w]);
    return r;
}

__global__ __launch_bounds__(256)
void softmax_kernel()
{
    float* p = g_energy + (size_t)blockIdx.x * HWSZ;
    const int tid = threadIdx.x;

    float v[4];
    float mx = -3.4e38f;
    #pragma unroll
    for (int i = 0; i < 4; i++) {
        v[i] = p[tid + i * 256];
        mx = fmaxf(mx, v[i]);
    }
    mx = block_reduce(mx, true);
    __syncthreads();   // shared red[] reused between the two reductions

    float s = 0.f;
    #pragma unroll
    for (int i = 0; i < 4; i++) {
        v[i] = __expf(v[i] - mx);
        s += v[i];
    }
    s = block_reduce(s, false);

    const float inv = 1.0f / s;
    #pragma unroll
    for (int i = 0; i < 4; i++) p[tid + i * 256] = v[i] * inv;
}

// ---------------------------------------------------------------------------
// Attended + residual:
// out[b][c][n] = x[b][c][n] + param * sum_m fval[b][c][m] * sim[b][n][m]
// ---------------------------------------------------------------------------
__global__ __launch_bounds__(256)
void attended_kernel(const float* __restrict__ x,
                     const float* __restrict__ param,
                     float* __restrict__ out)
{
    __shared__ float As[16][64];   // [m][c]
    __shared__ float Bs[16][64];   // [m][n]

    const int b  = blockIdx.z;
    const int c0 = blockIdx.y * 64;
    const int n0 = blockIdx.x * 64;
    const int tid = threadIdx.x;
    const int tx = tid & 15;       // n
    const int ty = tid >> 4;       // c

    const float* Vb = g_fval + b * (CCH * HWSZ);
    const float* Sb = g_energy + (size_t)b * HWSZ * HWSZ;

    float acc[4][4] = {};

    for (int k0 = 0; k0 < HWSZ; k0 += 16) {
        {   // V[c][m] -> As[m][c]
            const int c  = tid >> 2;
            const int mq = (tid & 3) * 4;
            float4 v = *reinterpret_cast<const float4*>(&Vb[(c0 + c) * HWSZ + k0 + mq]);
            As[mq + 0][c] = v.x; As[mq + 1][c] = v.y;
            As[mq + 2][c] = v.z; As[mq + 3][c] = v.w;
        }
        {   // S[n][m] -> Bs[m][n]
            const int n  = tid >> 2;
            const int mq = (tid & 3) * 4;
            float4 v = *reinterpret_cast<const float4*>(&Sb[(size_t)(n0 + n) * HWSZ + k0 + mq]);
            Bs[mq + 0][n] = v.x; Bs[mq + 1][n] = v.y;
            Bs[mq + 2][n] = v.z; Bs[mq + 3][n] = v.w;
        }
        __syncthreads();

        #pragma unroll
        for (int k = 0; k < 16; k++) {
            float a[4], bb[4];
            *reinterpret_cast<float4*>(a)  = *reinterpret_cast<const float4*>(&As[k][ty * 4]);
            *reinterpret_cast<float4*>(bb) = *reinterpret_cast<const float4*>(&Bs[k][tx * 4]);
            #pragma unroll
            for (int i = 0; i < 4; i++)
                #pragma unroll
                for (int j = 0; j < 4; j++)
                    acc[i][j] += a[i] * bb[j];
        }
        __syncthreads();
    }

    const float pscale = param[0];
    const float* xb = x   + b * (CCH * HWSZ);
    float*       ob = out + b * (CCH * HWSZ);
    #pragma unroll
    for (int i = 0; i < 4; i++) {
        const int row = (c0 + ty * 4 + i) * HWSZ + n0 + tx * 4;
        float4 xv = *reinterpret_cast<const float4*>(&xb[row]);
        float4 v  = make_float4(xv.x + pscale * acc[i][0],
                                xv.y + pscale * acc[i][1],
                                xv.z + pscale * acc[i][2],
                                xv.w + pscale * acc[i][3]);
        *reinterpret_cast<float4*>(&ob[row]) = v;
    }
}

// ---------------------------------------------------------------------------
extern "C" void kernel_launch(void* const* d_in, const int* in_sizes, int n_in,
                              void* d_out, int out_size)
{
    const float* x     = (const float*)d_in[0];
    const float* Wk    = (const float*)d_in[1];
    const float* bk    = (const float*)d_in[2];
    const float* Wp    = (const float*)d_in[3];
    const float* bp    = (const float*)d_in[4];
    const float* Wv    = (const float*)d_in[5];
    const float* bv    = (const float*)d_in[6];
    const float* param = (const float*)d_in[7];
    float* out = (float*)d_out;

    dim3 blk(256);

    // Projections (write to template-selected device globals)
    proj_kernel<RCH, 0><<<dim3(HWSZ / 64, RCH / 64, BATCH), blk>>>(x, Wk, bk);
    proj_kernel<RCH, 1><<<dim3(HWSZ / 64, RCH / 64, BATCH), blk>>>(x, Wp, bp);
    proj_kernel<CCH, 2><<<dim3(HWSZ / 64, CCH / 64, BATCH), blk>>>(x, Wv, bv);

    // Energy
    energy_kernel<<<dim3(HWSZ / 64, HWSZ / 64, BATCH), blk>>>();

    // Softmax (rows of 1024)
    softmax_kernel<<<dim3(BATCH * HWSZ), blk>>>();

    // Attended + residual
    attended_kernel<<<dim3(HWSZ / 64, CCH / 64, BATCH), blk>>>(x, param, out);
}

// round 4
// speedup vs baseline: 1.2893x; 1.2893x over previous
#include <cuda_runtime.h>

#define BATCH 32
#define CCH   512
#define RCH   256
#define HWSZ  1024

__device__ float g_fkey [BATCH * RCH * HWSZ];           // 32 MB  [b][r][n]
__device__ float g_fprod[BATCH * RCH * HWSZ];           // 32 MB  [b][r][m]
__device__ float g_fval [BATCH * CCH * HWSZ];           // 64 MB  [b][c][m]
__device__ float g_energy[(size_t)BATCH * HWSZ * HWSZ]; // 128 MB [b][n][m]

// ===========================================================================
// Shared 128x128x16 SGEMM skeleton: 256 threads, 8x8 per thread (4+4 split).
// Threads: tx = tid&15 (cols), ty = tid>>4 (rows).
// Per-thread rows: ty*4+i and 64+ty*4+i; cols: tx*4+j and 64+tx*4+j.
// ===========================================================================
__device__ __forceinline__ void mm_step(const float (*As)[128], const float (*Bs)[128],
                                        int tx, int ty, float acc[8][8])
{
    #pragma unroll
    for (int k = 0; k < 16; k++) {
        float a[8], b[8];
        *reinterpret_cast<float4*>(a)     = *reinterpret_cast<const float4*>(&As[k][ty * 4]);
        *reinterpret_cast<float4*>(a + 4) = *reinterpret_cast<const float4*>(&As[k][64 + ty * 4]);
        *reinterpret_cast<float4*>(b)     = *reinterpret_cast<const float4*>(&Bs[k][tx * 4]);
        *reinterpret_cast<float4*>(b + 4) = *reinterpret_cast<const float4*>(&Bs[k][64 + tx * 4]);
        #pragma unroll
        for (int i = 0; i < 8; i++)
            #pragma unroll
            for (int j = 0; j < 8; j++)
                acc[i][j] += a[i] * b[j];
    }
}

// ---------------------------------------------------------------------------
// Projection: out[b][o][n] = sum_c W[o][c] * x[b][c][n] + bias[o]
// W row-major [M x K] -> transposed scatter; x K-major -> direct copy.
// ---------------------------------------------------------------------------
template<int M, int WHICH>
__global__ __launch_bounds__(256)
void proj_kernel(const float* __restrict__ x,
                 const float* __restrict__ W,
                 const float* __restrict__ bias)
{
    float* out = (WHICH == 0) ? g_fkey : (WHICH == 1) ? g_fprod : g_fval;
    const int K = CCH;

    __shared__ float As[16][128];   // [k][m]
    __shared__ float Bs[16][128];   // [k][n]

    const int b  = blockIdx.z;
    const int m0 = blockIdx.y * 128;
    const int n0 = blockIdx.x * 128;
    const int tid = threadIdx.x;
    const int tx = tid & 15;
    const int ty = tid >> 4;

    const float* xb = x + b * (CCH * HWSZ);

    float acc[8][8] = {};

    for (int k0 = 0; k0 < K; k0 += 16) {
        // A: W[m][k] -> As[k][m], 2 float4 per thread
        {
            const int m  = tid >> 2;            // 0..63
            const int kq = (tid & 3) * 4;
            #pragma unroll
            for (int h = 0; h < 2; h++) {
                float4 v = *reinterpret_cast<const float4*>(&W[(m0 + h * 64 + m) * K + k0 + kq]);
                As[kq + 0][h * 64 + m] = v.x; As[kq + 1][h * 64 + m] = v.y;
                As[kq + 2][h * 64 + m] = v.z; As[kq + 3][h * 64 + m] = v.w;
            }
        }
        // B: direct copy, 2 float4 per thread
        {
            const int kr = tid >> 5;            // 0..7
            const int nq = (tid & 31) * 4;
            #pragma unroll
            for (int h = 0; h < 2; h++)
                *reinterpret_cast<float4*>(&Bs[kr + h * 8][nq]) =
                    *reinterpret_cast<const float4*>(&xb[(k0 + kr + h * 8) * HWSZ + n0 + nq]);
        }
        __syncthreads();
        mm_step(As, Bs, tx, ty, acc);
        __syncthreads();
    }

    float* ob = out + b * (M * HWSZ);
    #pragma unroll
    for (int ih = 0; ih < 2; ih++)
        #pragma unroll
        for (int i = 0; i < 4; i++) {
            const int r = m0 + ih * 64 + ty * 4 + i;
            const float bi = bias[r];
            #pragma unroll
            for (int jh = 0; jh < 2; jh++) {
                float4 v = make_float4(acc[ih * 4 + i][jh * 4 + 0] + bi,
                                       acc[ih * 4 + i][jh * 4 + 1] + bi,
                                       acc[ih * 4 + i][jh * 4 + 2] + bi,
                                       acc[ih * 4 + i][jh * 4 + 3] + bi);
                *reinterpret_cast<float4*>(&ob[r * HWSZ + n0 + jh * 64 + tx * 4]) = v;
            }
        }
}

// ---------------------------------------------------------------------------
// Energy: E[b][n][m] = sum_r fkey[b][r][n] * fprod[b][r][m]   (both K-major)
// ---------------------------------------------------------------------------
__global__ __launch_bounds__(256)
void energy_kernel()
{
    __shared__ float As[16][128];   // [r][n]
    __shared__ float Bs[16][128];   // [r][m]

    const int b  = blockIdx.z;
    const int n0 = blockIdx.y * 128;
    const int m0 = blockIdx.x * 128;
    const int tid = threadIdx.x;
    const int tx = tid & 15;
    const int ty = tid >> 4;

    const float* Kb = g_fkey  + b * (RCH * HWSZ);
    const float* Pb = g_fprod + b * (RCH * HWSZ);

    float acc[8][8] = {};

    for (int k0 = 0; k0 < RCH; k0 += 16) {
        const int kr = tid >> 5;
        const int cq = (tid & 31) * 4;
        #pragma unroll
        for (int h = 0; h < 2; h++) {
            *reinterpret_cast<float4*>(&As[kr + h * 8][cq]) =
                *reinterpret_cast<const float4*>(&Kb[(k0 + kr + h * 8) * HWSZ + n0 + cq]);
            *reinterpret_cast<float4*>(&Bs[kr + h * 8][cq]) =
                *reinterpret_cast<const float4*>(&Pb[(k0 + kr + h * 8) * HWSZ + m0 + cq]);
        }
        __syncthreads();
        mm_step(As, Bs, tx, ty, acc);
        __syncthreads();
    }

    float* Eb = g_energy + (size_t)b * HWSZ * HWSZ;
    #pragma unroll
    for (int ih = 0; ih < 2; ih++)
        #pragma unroll
        for (int i = 0; i < 4; i++) {
            const size_t r = (size_t)(n0 + ih * 64 + ty * 4 + i) * HWSZ;
            #pragma unroll
            for (int jh = 0; jh < 2; jh++)
                *reinterpret_cast<float4*>(&Eb[r + m0 + jh * 64 + tx * 4]) =
                    *reinterpret_cast<float4*>(&acc[ih * 4 + i][jh * 4]);
        }
}

// ---------------------------------------------------------------------------
// Softmax over last axis (rows of 1024), in place.
// ---------------------------------------------------------------------------
__device__ __forceinline__ float block_reduce(float v, bool do_max)
{
    __shared__ float red[8];
    #pragma unroll
    for (int o = 16; o > 0; o >>= 1) {
        const float other = __shfl_xor_sync(0xffffffffu, v, o);
        v = do_max ? fmaxf(v, other) : (v + other);
    }
    const int wid = threadIdx.x >> 5;
    if ((threadIdx.x & 31) == 0) red[wid] = v;
    __syncthreads();
    float r = red[0];
    #pragma unroll
    for (int w = 1; w < 8; w++) r = do_max ? fmaxf(r, red[w]) : (r + red[w]);
    return r;
}

__global__ __launch_bounds__(256)
void softmax_kernel()
{
    float* p = g_energy + (size_t)blockIdx.x * HWSZ;
    const int tid = threadIdx.x;

    float v[4];
    float mx = -3.4e38f;
    #pragma unroll
    for (int i = 0; i < 4; i++) {
        v[i] = p[tid + i * 256];
        mx = fmaxf(mx, v[i]);
    }
    mx = block_reduce(mx, true);
    __syncthreads();

    float s = 0.f;
    #pragma unroll
    for (int i = 0; i < 4; i++) {
        v[i] = __expf(v[i] - mx);
        s += v[i];
    }
    s = block_reduce(s, false);

    const float inv = 1.0f / s;
    #pragma unroll
    for (int i = 0; i < 4; i++) p[tid + i * 256] = v[i] * inv;
}

// ---------------------------------------------------------------------------
// Attended + residual:
// out[b][c][n] = x[b][c][n] + param * sum_m fval[b][c][m] * sim[b][n][m]
// Both operands m-major row layout -> transposed scatter into [m][*].
// ---------------------------------------------------------------------------
__global__ __launch_bounds__(256)
void attended_kernel(const float* __restrict__ x,
                     const float* __restrict__ param,
                     float* __restrict__ out)
{
    __shared__ float As[16][128];   // [m][c]
    __shared__ float Bs[16][128];   // [m][n]

    const int b  = blockIdx.z;
    const int c0 = blockIdx.y * 128;
    const int n0 = blockIdx.x * 128;
    const int tid = threadIdx.x;
    const int tx = tid & 15;
    const int ty = tid >> 4;

    const float* Vb = g_fval + b * (CCH * HWSZ);
    const float* Sb = g_energy + (size_t)b * HWSZ * HWSZ;

    float acc[8][8] = {};

    for (int k0 = 0; k0 < HWSZ; k0 += 16) {
        const int row = tid >> 2;           // 0..63
        const int mq  = (tid & 3) * 4;
        #pragma unroll
        for (int h = 0; h < 2; h++) {
            {   // V[c][m] -> As[m][c]
                float4 v = *reinterpret_cast<const float4*>(
                    &Vb[(c0 + h * 64 + row) * HWSZ + k0 + mq]);
                As[mq + 0][h * 64 + row] = v.x; As[mq + 1][h * 64 + row] = v.y;
                As[mq + 2][h * 64 + row] = v.z; As[mq + 3][h * 64 + row] = v.w;
            }
            {   // S[n][m] -> Bs[m][n]
                float4 v = *reinterpret_cast<const float4*>(
                    &Sb[(size_t)(n0 + h * 64 + row) * HWSZ + k0 + mq]);
                Bs[mq + 0][h * 64 + row] = v.x; Bs[mq + 1][h * 64 + row] = v.y;
                Bs[mq + 2][h * 64 + row] = v.z; Bs[mq + 3][h * 64 + row] = v.w;
            }
        }
        __syncthreads();
        mm_step(As, Bs, tx, ty, acc);
        __syncthreads();
    }

    const float pscale = param[0];
    const float* xb = x   + b * (CCH * HWSZ);
    float*       ob = out + b * (CCH * HWSZ);
    #pragma unroll
    for (int ih = 0; ih < 2; ih++)
        #pragma unroll
        for (int i = 0; i < 4; i++) {
            const int r = (c0 + ih * 64 + ty * 4 + i) * HWSZ + n0;
            #pragma unroll
            for (int jh = 0; jh < 2; jh++) {
                const int off = r + jh * 64 + tx * 4;
                float4 xv = *reinterpret_cast<const float4*>(&xb[off]);
                float4 v  = make_float4(xv.x + pscale * acc[ih * 4 + i][jh * 4 + 0],
                                        xv.y + pscale * acc[ih * 4 + i][jh * 4 + 1],
                                        xv.z + pscale * acc[ih * 4 + i][jh * 4 + 2],
                                        xv.w + pscale * acc[ih * 4 + i][jh * 4 + 3]);
                *reinterpret_cast<float4*>(&ob[off]) = v;
            }
        }
}

// ---------------------------------------------------------------------------
extern "C" void kernel_launch(void* const* d_in, const int* in_sizes, int n_in,
                              void* d_out, int out_size)
{
    const float* x     = (const float*)d_in[0];
    const float* Wk    = (const float*)d_in[1];
    const float* bk    = (const float*)d_in[2];
    const float* Wp    = (const float*)d_in[3];
    const float* bp    = (const float*)d_in[4];
    const float* Wv    = (const float*)d_in[5];
    const float* bv    = (const float*)d_in[6];
    const float* param = (const float*)d_in[7];
    float* out = (float*)d_out;

    dim3 blk(256);

    proj_kernel<RCH, 0><<<dim3(HWSZ / 128, RCH / 128, BATCH), blk>>>(x, Wk, bk);
    proj_kernel<RCH, 1><<<dim3(HWSZ / 128, RCH / 128, BATCH), blk>>>(x, Wp, bp);
    proj_kernel<CCH, 2><<<dim3(HWSZ / 128, CCH / 128, BATCH), blk>>>(x, Wv, bv);

    energy_kernel<<<dim3(HWSZ / 128, HWSZ / 128, BATCH), blk>>>();

    softmax_kernel<<<dim3(BATCH * HWSZ), blk>>>();

    attended_kernel<<<dim3(HWSZ / 128, CCH / 128, BATCH), blk>>>(x, param, out);
}

// round 7
// speedup vs baseline: 2.4052x; 1.8656x over previous
#include <cuda_runtime.h>
#include <cstdint>

#define BATCH 32
#define CCH   512
#define RCH   256
#define HWSZ  1024

// Scratch (device globals; alloc-free rule)
__device__ float g_fkey [BATCH * RCH * HWSZ];           // [b][r][n]
__device__ float g_fprod[BATCH * RCH * HWSZ];           // [b][r][m]
__device__ float g_fval [BATCH * CCH * HWSZ];           // [b][c][m]
__device__ float g_energy[(size_t)BATCH * HWSZ * HWSZ]; // [b][n][m]

// ---------------------------------------------------------------------------
// tf32 helpers (legacy HMMA path — compiles for plain sm_100)
// ---------------------------------------------------------------------------
__device__ __forceinline__ uint32_t f2tf32(float f) {
    uint32_t u;
    asm("cvt.rna.tf32.f32 %0, %1;" : "=r"(u) : "f"(f));
    return u;
}

__device__ __forceinline__ void mma_tf32(float c[4], const uint32_t a[4], const uint32_t b[2]) {
    asm volatile(
        "mma.sync.aligned.m16n8k8.row.col.f32.tf32.tf32.f32 "
        "{%0,%1,%2,%3}, {%4,%5,%6,%7}, {%8,%9}, {%0,%1,%2,%3};"
        : "+f"(c[0]), "+f"(c[1]), "+f"(c[2]), "+f"(c[3])
        : "r"(a[0]), "r"(a[1]), "r"(a[2]), "r"(a[3]), "r"(b[0]), "r"(b[1]));
}

// ---------------------------------------------------------------------------
// Tile geometry: BM=BN=128, BK=32; 256 threads = 8 warps as 2(m) x 4(n).
// Warp tile 64x32 = 4x4 mma(m16n8k8) per 8-deep k-step; 4 k-steps per chunk.
// smem row stride 136 floats -> conflict-free fragment loads
// (A-frag/B-frag bank = tig*8 + g, all 32 distinct).
// ---------------------------------------------------------------------------
#define SPAD 136

// Direct copy: src is k-major [k][n] (row stride ld); tile 32 x 128.
__device__ __forceinline__ void load_direct(uint32_t (*S)[SPAD],
                                            const float* __restrict__ src,
                                            size_t ld, int tid)
{
    const int kr = tid >> 3;            // 0..31
    const int nq = (tid & 7) * 16;      // 0..112
    #pragma unroll
    for (int j = 0; j < 4; j++) {
        float4 v = *reinterpret_cast<const float4*>(src + (size_t)kr * ld + nq + j * 4);
        S[kr][nq + j * 4 + 0] = f2tf32(v.x);
        S[kr][nq + j * 4 + 1] = f2tf32(v.y);
        S[kr][nq + j * 4 + 2] = f2tf32(v.z);
        S[kr][nq + j * 4 + 3] = f2tf32(v.w);
    }
}

// Transposed scatter: src is m-major [m][k] (row stride ld) -> S[k][m]; 128 x 32.
__device__ __forceinline__ void load_scatter(uint32_t (*S)[SPAD],
                                             const float* __restrict__ src,
                                             size_t ld, int tid)
{
    const int m  = tid >> 1;            // 0..127
    const int kq = (tid & 1) * 16;      // 0 or 16
    #pragma unroll
    for (int j = 0; j < 4; j++) {
        float4 v = *reinterpret_cast<const float4*>(src + (size_t)m * ld + kq + j * 4);
        S[kq + j * 4 + 0][m] = f2tf32(v.x);
        S[kq + j * 4 + 1][m] = f2tf32(v.y);
        S[kq + j * 4 + 2][m] = f2tf32(v.z);
        S[kq + j * 4 + 3][m] = f2tf32(v.w);
    }
}

// One BK=32 chunk of warp-level MMAs.
__device__ __forceinline__ void mma_chunk(const uint32_t (*As)[SPAD],
                                          const uint32_t (*Bs)[SPAD],
                                          float acc[4][4][4],
                                          int wm, int wn, int g, int tig)
{
    #pragma unroll
    for (int kk = 0; kk < 4; kk++) {
        const int k = kk * 8;
        uint32_t a[4][4], b[4][2];
        #pragma unroll
        for (int mi = 0; mi < 4; mi++) {
            const int mR = wm + mi * 16 + g;
            a[mi][0] = As[k + tig][mR];
            a[mi][1] = As[k + tig][mR + 8];
            a[mi][2] = As[k + tig + 4][mR];
            a[mi][3] = As[k + tig + 4][mR + 8];
        }
        #pragma unroll
        for (int ni = 0; ni < 4; ni++) {
            const int nC = wn + ni * 8 + g;
            b[ni][0] = Bs[k + tig][nC];
            b[ni][1] = Bs[k + tig + 4][nC];
        }
        #pragma unroll
        for (int mi = 0; mi < 4; mi++)
            #pragma unroll
            for (int ni = 0; ni < 4; ni++)
                mma_tf32(acc[mi][ni], a[mi], b[ni]);
    }
}

// ---------------------------------------------------------------------------
// Projection: out[b][o][n] = sum_c W[o][c] * x[b][c][n] + bias[o]
// ---------------------------------------------------------------------------
template<int M, int WHICH>
__global__ __launch_bounds__(256)
void proj_kernel(const float* __restrict__ x,
                 const float* __restrict__ W,
                 const float* __restrict__ bias)
{
    float* out = (WHICH == 0) ? g_fkey : (WHICH == 1) ? g_fprod : g_fval;

    __shared__ uint32_t As[32][SPAD];   // [k][m]  (W transposed)
    __shared__ uint32_t Bs[32][SPAD];   // [k][n]  (x direct)

    const int b  = blockIdx.z;
    const int m0 = blockIdx.y * 128;
    const int n0 = blockIdx.x * 128;
    const int tid = threadIdx.x;
    const int wid = tid >> 5, lane = tid & 31;
    const int wm = (wid >> 2) * 64, wn = (wid & 3) * 32;
    const int g = lane >> 2, tig = lane & 3;

    const float* xb = x + (size_t)b * CCH * HWSZ;

    float acc[4][4][4] = {};

    for (int k0 = 0; k0 < CCH; k0 += 32) {
        load_scatter(As, W + (size_t)m0 * CCH + k0, CCH, tid);
        load_direct (Bs, xb + (size_t)k0 * HWSZ + n0, HWSZ, tid);
        __syncthreads();
        mma_chunk(As, Bs, acc, wm, wn, g, tig);
        __syncthreads();
    }

    float* ob = out + (size_t)b * M * HWSZ;
    #pragma unroll
    for (int mi = 0; mi < 4; mi++) {
        const int r = m0 + wm + mi * 16 + g;
        const float b0 = bias[r], b1 = bias[r + 8];
        #pragma unroll
        for (int ni = 0; ni < 4; ni++) {
            const int col = n0 + wn + ni * 8 + tig * 2;
            *reinterpret_cast<float2*>(&ob[(size_t)r * HWSZ + col]) =
                make_float2(acc[mi][ni][0] + b0, acc[mi][ni][1] + b0);
            *reinterpret_cast<float2*>(&ob[(size_t)(r + 8) * HWSZ + col]) =
                make_float2(acc[mi][ni][2] + b1, acc[mi][ni][3] + b1);
        }
    }
}

// ---------------------------------------------------------------------------
// Energy: E[b][n][m] = sum_r fkey[b][r][n] * fprod[b][r][m]
// ---------------------------------------------------------------------------
__global__ __launch_bounds__(256)
void energy_kernel()
{
    __shared__ uint32_t As[32][SPAD];   // [r][n]
    __shared__ uint32_t Bs[32][SPAD];   // [r][m]

    const int b  = blockIdx.z;
    const int n0 = blockIdx.y * 128;
    const int m0 = blockIdx.x * 128;
    const int tid = threadIdx.x;
    const int wid = tid >> 5, lane = tid & 31;
    const int wm = (wid >> 2) * 64, wn = (wid & 3) * 32;
    const int g = lane >> 2, tig = lane & 3;

    const float* Kb = g_fkey  + (size_t)b * RCH * HWSZ;
    const float* Pb = g_fprod + (size_t)b * RCH * HWSZ;

    float acc[4][4][4] = {};

    for (int k0 = 0; k0 < RCH; k0 += 32) {
        load_direct(As, Kb + (size_t)k0 * HWSZ + n0, HWSZ, tid);
        load_direct(Bs, Pb + (size_t)k0 * HWSZ + m0, HWSZ, tid);
        __syncthreads();
        mma_chunk(As, Bs, acc, wm, wn, g, tig);
        __syncthreads();
    }

    float* Eb = g_energy + (size_t)b * HWSZ * HWSZ;
    #pragma unroll
    for (int mi = 0; mi < 4; mi++) {
        const int r = n0 + wm + mi * 16 + g;
        #pragma unroll
        for (int ni = 0; ni < 4; ni++) {
            const int col = m0 + wn + ni * 8 + tig * 2;
            *reinterpret_cast<float2*>(&Eb[(size_t)r * HWSZ + col]) =
                make_float2(acc[mi][ni][0], acc[mi][ni][1]);
            *reinterpret_cast<float2*>(&Eb[(size_t)(r + 8) * HWSZ + col]) =
                make_float2(acc[mi][ni][2], acc[mi][ni][3]);
        }
    }
}

// ---------------------------------------------------------------------------
// Softmax over rows of 1024, in place on g_energy.
// ---------------------------------------------------------------------------
__device__ __forceinline__ float block_reduce(float v, bool do_max)
{
    __shared__ float red[8];
    #pragma unroll
    for (int o = 16; o > 0; o >>= 1) {
        const float other = __shfl_xor_sync(0xffffffffu, v, o);
        v = do_max ? fmaxf(v, other) : (v + other);
    }
    const int wid = threadIdx.x >> 5;
    if ((threadIdx.x & 31) == 0) red[wid] = v;
    __syncthreads();
    float r = red[0];
    #pragma unroll
    for (int w = 1; w < 8; w++) r = do_max ? fmaxf(r, red[w]) : (r + red[w]);
    return r;
}

__global__ __launch_bounds__(256)
void softmax_kernel()
{
    float* p = g_energy + (size_t)blockIdx.x * HWSZ;
    const int tid = threadIdx.x;

    float v[4];
    float mx = -3.4e38f;
    #pragma unroll
    for (int i = 0; i < 4; i++) {
        v[i] = p[tid + i * 256];
        mx = fmaxf(mx, v[i]);
    }
    mx = block_reduce(mx, true);
    __syncthreads();

    float s = 0.f;
    #pragma unroll
    for (int i = 0; i < 4; i++) {
        v[i] = __expf(v[i] - mx);
        s += v[i];
    }
    s = block_reduce(s, false);

    const float inv = 1.0f / s;
    #pragma unroll
    for (int i = 0; i < 4; i++) p[tid + i * 256] = v[i] * inv;
}

// ---------------------------------------------------------------------------
// Attended + residual:
// out[b][c][n] = x[b][c][n] + param * sum_m fval[b][c][m] * sim[b][n][m]
// ---------------------------------------------------------------------------
__global__ __launch_bounds__(256)
void attended_kernel(const float* __restrict__ x,
                     const float* __restrict__ param,
                     float* __restrict__ out)
{
    __shared__ uint32_t As[32][SPAD];   // [m_pix][c]  (fval transposed)
    __shared__ uint32_t Bs[32][SPAD];   // [m_pix][n]  (S transposed)

    const int b  = blockIdx.z;
    const int c0 = blockIdx.y * 128;
    const int n0 = blockIdx.x * 128;
    const int tid = threadIdx.x;
    const int wid = tid >> 5, lane = tid & 31;
    const int wm = (wid >> 2) * 64, wn = (wid & 3) * 32;
    const int g = lane >> 2, tig = lane & 3;

    const float* Vb = g_fval + (size_t)b * CCH * HWSZ;
    const float* Sb = g_energy + (size_t)b * HWSZ * HWSZ;

    float acc[4][4][4] = {};

    for (int k0 = 0; k0 < HWSZ; k0 += 32) {
        load_scatter(As, Vb + (size_t)c0 * HWSZ + k0, HWSZ, tid);
        load_scatter(Bs, Sb + (size_t)n0 * HWSZ + k0, HWSZ, tid);
        __syncthreads();
        mma_chunk(As, Bs, acc, wm, wn, g, tig);
        __syncthreads();
    }

    const float ps = param[0];
    const float* xb = x   + (size_t)b * CCH * HWSZ;
    float*       ob = out + (size_t)b * CCH * HWSZ;
    #pragma unroll
    for (int mi = 0; mi < 4; mi++) {
        const int r = c0 + wm + mi * 16 + g;
        #pragma unroll
        for (int ni = 0; ni < 4; ni++) {
            const int col = n0 + wn + ni * 8 + tig * 2;
            {
                const size_t off = (size_t)r * HWSZ + col;
                float2 xv = *reinterpret_cast<const float2*>(&xb[off]);
                *reinterpret_cast<float2*>(&ob[off]) =
                    make_float2(xv.x + ps * acc[mi][ni][0],
                                xv.y + ps * acc[mi][ni][1]);
            }
            {
                const size_t off = (size_t)(r + 8) * HWSZ + col;
                float2 xv = *reinterpret_cast<const float2*>(&xb[off]);
                *reinterpret_cast<float2*>(&ob[off]) =
                    make_float2(xv.x + ps * acc[mi][ni][2],
                                xv.y + ps * acc[mi][ni][3]);
            }
        }
    }
}

// ---------------------------------------------------------------------------
extern "C" void kernel_launch(void* const* d_in, const int* in_sizes, int n_in,
                              void* d_out, int out_size)
{
    const float* x     = (const float*)d_in[0];
    const float* Wk    = (const float*)d_in[1];
    const float* bk    = (const float*)d_in[2];
    const float* Wp    = (const float*)d_in[3];
    const float* bp    = (const float*)d_in[4];
    const float* Wv    = (const float*)d_in[5];
    const float* bv    = (const float*)d_in[6];
    const float* param = (const float*)d_in[7];
    float* out = (float*)d_out;

    dim3 blk(256);

    proj_kernel<RCH, 0><<<dim3(HWSZ / 128, RCH / 128, BATCH), blk>>>(x, Wk, bk);
    proj_kernel<RCH, 1><<<dim3(HWSZ / 128, RCH / 128, BATCH), blk>>>(x, Wp, bp);
    proj_kernel<CCH, 2><<<dim3(HWSZ / 128, CCH / 128, BATCH), blk>>>(x, Wv, bv);

    energy_kernel<<<dim3(HWSZ / 128, HWSZ / 128, BATCH), blk>>>();

    softmax_kernel<<<dim3(BATCH * HWSZ), blk>>>();

    attended_kernel<<<dim3(HWSZ / 128, CCH / 128, BATCH), blk>>>(x, param, out);
}

// round 8
// speedup vs baseline: 4.2559x; 1.7694x over previous
#include <cuda_runtime.h>
#include <cstdint>

#define BATCH 32
#define CCH   512
#define RCH   256
#define HWSZ  1024

// Scratch (device globals; alloc-free rule). All GEMM operands k-minor.
__device__ float g_xT    [BATCH * HWSZ * CCH];           // [b][n][c]
__device__ float g_fkeyT [BATCH * HWSZ * RCH];           // [b][n][r]
__device__ float g_fprodT[BATCH * HWSZ * RCH];           // [b][m][r]
__device__ float g_fval  [BATCH * CCH * HWSZ];           // [b][c][m]
__device__ float g_energy[(size_t)BATCH * HWSZ * HWSZ];  // [b][n][m]

// ---------------------------------------------------------------------------
// PTX helpers
// ---------------------------------------------------------------------------
__device__ __forceinline__ uint32_t s2u(const void* p) {
    uint32_t a;
    asm("{ .reg .u64 t; cvta.to.shared.u64 t, %1; cvt.u32.u64 %0, t; }" : "=r"(a) : "l"(p));
    return a;
}
__device__ __forceinline__ void cp_async16(uint32_t dst, const void* src) {
    asm volatile("cp.async.cg.shared.global [%0], [%1], 16;" :: "r"(dst), "l"(src));
}
#define CP_COMMIT() asm volatile("cp.async.commit_group;" ::: "memory")
#define CP_WAIT1()  asm volatile("cp.async.wait_group 1;" ::: "memory")
#define CP_WAIT0()  asm volatile("cp.async.wait_group 0;" ::: "memory")

__device__ __forceinline__ void mma_tf32(float c[4], const uint32_t a[4], const uint32_t b[2]) {
    asm volatile(
        "mma.sync.aligned.m16n8k8.row.col.f32.tf32.tf32.f32 "
        "{%0,%1,%2,%3}, {%4,%5,%6,%7}, {%8,%9}, {%0,%1,%2,%3};"
        : "+f"(c[0]), "+f"(c[1]), "+f"(c[2]), "+f"(c[3])
        : "r"(a[0]), "r"(a[1]), "r"(a[2]), "r"(a[3]), "r"(b[0]), "r"(b[1]));
}

// ---------------------------------------------------------------------------
// GEMM core: D[128x128] = A[128xK] * B[128xK]^T, both operands k-minor
// (row = output dim, 32-float k-chunks). BK=32, 2-stage cp.async pipeline.
// Tiles in dyn smem, XOR swizzle col' = col ^ 4*(row&7) -> conflict-free
// fragment loads + 16B-aligned async copies.
// 256 threads = 8 warps as 2(m) x 4(n); warp tile 64x32.
// ---------------------------------------------------------------------------
#define TILE_WORDS (128 * 32)          // 16 KB per tile
#define STAGE_WORDS (2 * TILE_WORDS)   // A + B per stage

extern __shared__ uint32_t smp[];      // [2][2][128*32]

// Issue one 128x32 tile stage-in: 4 cp.async(16B) per thread.
__device__ __forceinline__ void stage_tile(uint32_t sbase, const float* src,
                                           size_t ld, int tid)
{
    #pragma unroll
    for (int v = 0; v < 4; v++) {
        const int idx = tid + v * 256;        // 0..1023
        const int row = idx >> 3;             // 0..127
        const int cg  = idx & 7;              // float4 group within row
        const uint32_t col4 = (cg * 4) ^ ((row & 7) * 4);
        cp_async16(sbase + (row * 32 + col4) * 4, src + (size_t)row * ld + cg * 4);
    }
}

__device__ __forceinline__ void mma_chunk(const uint32_t* As, const uint32_t* Bs,
                                          float acc[4][4][4],
                                          int wm, int wn, int g, int tig)
{
    const int x4g = 4 * g;
    #pragma unroll
    for (int kk = 0; kk < 4; kk++) {
        const int k  = kk * 8;
        const int c0 = (k + tig) ^ x4g;
        const int c1 = (k + 4 + tig) ^ x4g;
        uint32_t a[4][4], b[4][2];
        #pragma unroll
        for (int mi = 0; mi < 4; mi++) {
            const int r = (wm + mi * 16 + g) * 32;
            a[mi][0] = As[r + c0];
            a[mi][1] = As[r + 256 + c0];      // +8 rows
            a[mi][2] = As[r + c1];
            a[mi][3] = As[r + 256 + c1];
        }
        #pragma unroll
        for (int ni = 0; ni < 4; ni++) {
            const int r = (wn + ni * 8 + g) * 32;
            b[ni][0] = Bs[r + c0];
            b[ni][1] = Bs[r + c1];
        }
        #pragma unroll
        for (int mi = 0; mi < 4; mi++)
            #pragma unroll
            for (int ni = 0; ni < 4; ni++)
                mma_tf32(acc[mi][ni], a[mi], b[ni]);
    }
}

__device__ __forceinline__ void gemm_tn(const float* __restrict__ A, size_t lda,
                                        const float* __restrict__ B, size_t ldb,
                                        int nIter, float acc[4][4][4],
                                        int wm, int wn, int g, int tig)
{
    const int tid = threadIdx.x;
    const uint32_t sm0 = s2u(smp);

    stage_tile(sm0, A, lda, tid);
    stage_tile(sm0 + TILE_WORDS * 4, B, ldb, tid);
    CP_COMMIT();

    for (int it = 0; it < nIter; ++it) {
        if (it + 1 < nIter) {
            const uint32_t sb = sm0 + ((it + 1) & 1) * (STAGE_WORDS * 4);
            stage_tile(sb, A + (it + 1) * 32, lda, tid);
            stage_tile(sb + TILE_WORDS * 4, B + (it + 1) * 32, ldb, tid);
            CP_COMMIT();
            CP_WAIT1();
        } else {
            CP_WAIT0();
        }
        __syncthreads();
        const uint32_t* cur = smp + (it & 1) * STAGE_WORDS;
        mma_chunk(cur, cur + TILE_WORDS, acc, wm, wn, g, tig);
        __syncthreads();
    }
}

// ---------------------------------------------------------------------------
// Transpose: xT[b][n][c] = x[b][c][n]
// ---------------------------------------------------------------------------
__global__ __launch_bounds__(256)
void transpose_kernel(const float* __restrict__ x)
{
    __shared__ float t[32][33];
    const int b  = blockIdx.z;
    const int n0 = blockIdx.x * 32;
    const int c0 = blockIdx.y * 32;
    const int tx = threadIdx.x & 31;
    const int ty = threadIdx.x >> 5;

    const float* xb = x + (size_t)b * CCH * HWSZ;
    #pragma unroll
    for (int i = 0; i < 4; i++)
        t[ty + i * 8][tx] = xb[(size_t)(c0 + ty + i * 8) * HWSZ + n0 + tx];
    __syncthreads();
    float* xT = g_xT + (size_t)b * HWSZ * CCH;
    #pragma unroll
    for (int i = 0; i < 4; i++)
        xT[(size_t)(n0 + ty + i * 8) * CCH + c0 + tx] = t[tx][ty + i * 8];
}

// ---------------------------------------------------------------------------
// proj_kp: D[n][r] = sum_c xT[n][c] * W[r][c] + bias[r] -> fkeyT / fprodT
// (operand roles swapped so D rows = n; epilogue writes row-major)
// ---------------------------------------------------------------------------
template<int WHICH>
__global__ __launch_bounds__(256)
void proj_kp_kernel(const float* __restrict__ W, const float* __restrict__ bias)
{
    const int b  = blockIdx.z;
    const int n0 = blockIdx.x * 128;
    const int r0 = blockIdx.y * 128;
    const int tid = threadIdx.x;
    const int wid = tid >> 5, lane = tid & 31;
    const int wm = (wid >> 2) * 64, wn = (wid & 3) * 32;
    const int g = lane >> 2, tig = lane & 3;

    float acc[4][4][4] = {};
    gemm_tn(g_xT + (size_t)b * HWSZ * CCH + (size_t)n0 * CCH, CCH,
            W + (size_t)r0 * CCH, CCH, CCH / 32, acc, wm, wn, g, tig);

    float* dst = (WHICH == 0 ? g_fkeyT : g_fprodT);
    #pragma unroll
    for (int ni = 0; ni < 4; ni++) {
        const int col = r0 + wn + ni * 8 + tig * 2;
        const float2 bv = *reinterpret_cast<const float2*>(&bias[col]);
        #pragma unroll
        for (int mi = 0; mi < 4; mi++) {
            const int row = n0 + wm + mi * 16 + g;
            *reinterpret_cast<float2*>(&dst[((size_t)b * HWSZ + row) * RCH + col]) =
                make_float2(acc[mi][ni][0] + bv.x, acc[mi][ni][1] + bv.y);
            *reinterpret_cast<float2*>(&dst[((size_t)b * HWSZ + row + 8) * RCH + col]) =
                make_float2(acc[mi][ni][2] + bv.x, acc[mi][ni][3] + bv.y);
        }
    }
}

// ---------------------------------------------------------------------------
// proj_v: D[c][m] = sum_ci Wv[c][ci] * xT[m][ci] + bias[c] -> fval[b][c][m]
// ---------------------------------------------------------------------------
__global__ __launch_bounds__(256)
void proj_v_kernel(const float* __restrict__ Wv, const float* __restrict__ bias)
{
    const int b  = blockIdx.z;
    const int m0 = blockIdx.x * 128;
    const int c0 = blockIdx.y * 128;
    const int tid = threadIdx.x;
    const int wid = tid >> 5, lane = tid & 31;
    const int wm = (wid >> 2) * 64, wn = (wid & 3) * 32;
    const int g = lane >> 2, tig = lane & 3;

    float acc[4][4][4] = {};
    gemm_tn(Wv + (size_t)c0 * CCH, CCH,
            g_xT + (size_t)b * HWSZ * CCH + (size_t)m0 * CCH, CCH,
            CCH / 32, acc, wm, wn, g, tig);

    #pragma unroll
    for (int mi = 0; mi < 4; mi++) {
        const int row = c0 + wm + mi * 16 + g;
        const float b0 = bias[row], b1 = bias[row + 8];
        #pragma unroll
        for (int ni = 0; ni < 4; ni++) {
            const int col = m0 + wn + ni * 8 + tig * 2;
            *reinterpret_cast<float2*>(&g_fval[((size_t)b * CCH + row) * HWSZ + col]) =
                make_float2(acc[mi][ni][0] + b0, acc[mi][ni][1] + b0);
            *reinterpret_cast<float2*>(&g_fval[((size_t)b * CCH + row + 8) * HWSZ + col]) =
                make_float2(acc[mi][ni][2] + b1, acc[mi][ni][3] + b1);
        }
    }
}

// ---------------------------------------------------------------------------
// energy: E[n][m] = sum_r fkeyT[n][r] * fprodT[m][r]
// ---------------------------------------------------------------------------
__global__ __launch_bounds__(256)
void energy_kernel()
{
    const int b  = blockIdx.z;
    const int m0 = blockIdx.x * 128;
    const int n0 = blockIdx.y * 128;
    const int tid = threadIdx.x;
    const int wid = tid >> 5, lane = tid & 31;
    const int wm = (wid >> 2) * 64, wn = (wid & 3) * 32;
    const int g = lane >> 2, tig = lane & 3;

    float acc[4][4][4] = {};
    gemm_tn(g_fkeyT  + ((size_t)b * HWSZ + n0) * RCH, RCH,
            g_fprodT + ((size_t)b * HWSZ + m0) * RCH, RCH,
            RCH / 32, acc, wm, wn, g, tig);

    float* Eb = g_energy + (size_t)b * HWSZ * HWSZ;
    #pragma unroll
    for (int mi = 0; mi < 4; mi++) {
        const int row = n0 + wm + mi * 16 + g;
        #pragma unroll
        for (int ni = 0; ni < 4; ni++) {
            const int col = m0 + wn + ni * 8 + tig * 2;
            *reinterpret_cast<float2*>(&Eb[(size_t)row * HWSZ + col]) =
                make_float2(acc[mi][ni][0], acc[mi][ni][1]);
            *reinterpret_cast<float2*>(&Eb[(size_t)(row + 8) * HWSZ + col]) =
                make_float2(acc[mi][ni][2], acc[mi][ni][3]);
        }
    }
}

// ---------------------------------------------------------------------------
// softmax over rows of 1024, in place on g_energy
// ---------------------------------------------------------------------------
__device__ __forceinline__ float block_reduce(float v, bool do_max)
{
    __shared__ float red[8];
    #pragma unroll
    for (int o = 16; o > 0; o >>= 1) {
        const float other = __shfl_xor_sync(0xffffffffu, v, o);
        v = do_max ? fmaxf(v, other) : (v + other);
    }
    const int wid = threadIdx.x >> 5;
    if ((threadIdx.x & 31) == 0) red[wid] = v;
    __syncthreads();
    float r = red[0];
    #pragma unroll
    for (int w = 1; w < 8; w++) r = do_max ? fmaxf(r, red[w]) : (r + red[w]);
    return r;
}

__global__ __launch_bounds__(256)
void softmax_kernel()
{
    float* p = g_energy + (size_t)blockIdx.x * HWSZ;
    const int tid = threadIdx.x;

    float v[4];
    float mx = -3.4e38f;
    #pragma unroll
    for (int i = 0; i < 4; i++) {
        v[i] = p[tid + i * 256];
        mx = fmaxf(mx, v[i]);
    }
    mx = block_reduce(mx, true);
    __syncthreads();

    float s = 0.f;
    #pragma unroll
    for (int i = 0; i < 4; i++) {
        v[i] = __expf(v[i] - mx);
        s += v[i];
    }
    s = block_reduce(s, false);

    const float inv = 1.0f / s;
    #pragma unroll
    for (int i = 0; i < 4; i++) p[tid + i * 256] = v[i] * inv;
}

// ---------------------------------------------------------------------------
// attended: D[c][n] = sum_m fval[c][m] * S[n][m];
// out[c][n] = x[c][n] + param * D[c][n]
// ---------------------------------------------------------------------------
__global__ __launch_bounds__(256)
void attended_kernel(const float* __restrict__ x,
                     const float* __restrict__ param,
                     float* __restrict__ out)
{
    const int b  = blockIdx.z;
    const int n0 = blockIdx.x * 128;
    const int c0 = blockIdx.y * 128;
    const int tid = threadIdx.x;
    const int wid = tid >> 5, lane = tid & 31;
    const int wm = (wid >> 2) * 64, wn = (wid & 3) * 32;
    const int g = lane >> 2, tig = lane & 3;

    float acc[4][4][4] = {};
    gemm_tn(g_fval + ((size_t)b * CCH + c0) * HWSZ, HWSZ,
            g_energy + ((size_t)b * HWSZ + n0) * HWSZ, HWSZ,
            HWSZ / 32, acc, wm, wn, g, tig);

    const float ps = param[0];
    const float* xb = x   + (size_t)b * CCH * HWSZ;
    float*       ob = out + (size_t)b * CCH * HWSZ;
    #pragma unroll
    for (int mi = 0; mi < 4; mi++) {
        const int row = c0 + wm + mi * 16 + g;
        #pragma unroll
        for (int ni = 0; ni < 4; ni++) {
            const int col = n0 + wn + ni * 8 + tig * 2;
            {
                const size_t off = (size_t)row * HWSZ + col;
                float2 xv = *reinterpret_cast<const float2*>(&xb[off]);
                *reinterpret_cast<float2*>(&ob[off]) =
                    make_float2(xv.x + ps * acc[mi][ni][0],
                                xv.y + ps * acc[mi][ni][1]);
            }
            {
                const size_t off = (size_t)(row + 8) * HWSZ + col;
                float2 xv = *reinterpret_cast<const float2*>(&xb[off]);
                *reinterpret_cast<float2*>(&ob[off]) =
                    make_float2(xv.x + ps * acc[mi][ni][2],
                                xv.y + ps * acc[mi][ni][3]);
            }
        }
    }
}

// ---------------------------------------------------------------------------
extern "C" void kernel_launch(void* const* d_in, const int* in_sizes, int n_in,
                              void* d_out, int out_size)
{
    const float* x     = (const float*)d_in[0];
    const float* Wk    = (const float*)d_in[1];
    const float* bk    = (const float*)d_in[2];
    const float* Wp    = (const float*)d_in[3];
    const float* bp    = (const float*)d_in[4];
    const float* Wv    = (const float*)d_in[5];
    const float* bv    = (const float*)d_in[6];
    const float* param = (const float*)d_in[7];
    float* out = (float*)d_out;

    const int DSM = 2 * STAGE_WORDS * 4;   // 64 KB dynamic smem
    cudaFuncSetAttribute(proj_kp_kernel<0>, cudaFuncAttributeMaxDynamicSharedMemorySize, DSM);
    cudaFuncSetAttribute(proj_kp_kernel<1>, cudaFuncAttributeMaxDynamicSharedMemorySize, DSM);
    cudaFuncSetAttribute(proj_v_kernel,     cudaFuncAttributeMaxDynamicSharedMemorySize, DSM);
    cudaFuncSetAttribute(energy_kernel,     cudaFuncAttributeMaxDynamicSharedMemorySize, DSM);
    cudaFuncSetAttribute(attended_kernel,   cudaFuncAttributeMaxDynamicSharedMemorySize, DSM);

    transpose_kernel<<<dim3(HWSZ / 32, CCH / 32, BATCH), 256>>>(x);

    proj_kp_kernel<0><<<dim3(HWSZ / 128, RCH / 128, BATCH), 256, DSM>>>(Wk, bk);
    proj_kp_kernel<1><<<dim3(HWSZ / 128, RCH / 128, BATCH), 256, DSM>>>(Wp, bp);
    proj_v_kernel    <<<dim3(HWSZ / 128, CCH / 128, BATCH), 256, DSM>>>(Wv, bv);

    energy_kernel<<<dim3(HWSZ / 128, HWSZ / 128, BATCH), 256, DSM>>>();

    softmax_kernel<<<dim3(BATCH * HWSZ), 256>>>();

    attended_kernel<<<dim3(HWSZ / 128, CCH / 128, BATCH), 256, DSM>>>(x, param, out);
}

// round 10
// speedup vs baseline: 4.6784x; 1.0993x over previous
#include <cuda_runtime.h>
#include <cstdint>

#define BATCH 32
#define CCH   512
#define RCH   256
#define HWSZ  1024

// Scratch (device globals; alloc-free rule). All GEMM operands k-minor.
__device__ float g_xT    [BATCH * HWSZ * CCH];           // [b][n][c]
__device__ float g_fkeyT [BATCH * HWSZ * RCH];           // [b][n][r]
__device__ float g_fprodT[BATCH * HWSZ * RCH];           // [b][m][r]
__device__ float g_fval  [BATCH * CCH * HWSZ];           // [b][c][m]
__device__ float g_energy[(size_t)BATCH * HWSZ * HWSZ];  // [b][n][m] -> exp(s-SH)
__device__ float g_epart [BATCH * HWSZ * 8];             // per-mtile row sums
__device__ float g_inv   [BATCH * HWSZ];                 // 1/rowsum

#define EXP_SHIFT 60.0f

// ---------------------------------------------------------------------------
// PTX helpers
// ---------------------------------------------------------------------------
__device__ __forceinline__ uint32_t s2u(const void* p) {
    uint32_t a;
    asm("{ .reg .u64 t; cvta.to.shared.u64 t, %1; cvt.u32.u64 %0, t; }" : "=r"(a) : "l"(p));
    return a;
}
__device__ __forceinline__ void cp_async16(uint32_t dst, const void* src) {
    asm volatile("cp.async.cg.shared.global [%0], [%1], 16;" :: "r"(dst), "l"(src));
}
#define CP_COMMIT() asm volatile("cp.async.commit_group;" ::: "memory")
#define CP_WAIT1()  asm volatile("cp.async.wait_group 1;" ::: "memory")
#define CP_WAIT0()  asm volatile("cp.async.wait_group 0;" ::: "memory")

__device__ __forceinline__ void mma_tf32(float c[4], const uint32_t a[4], const uint32_t b[2]) {
    asm volatile(
        "mma.sync.aligned.m16n8k8.row.col.f32.tf32.tf32.f32 "
        "{%0,%1,%2,%3}, {%4,%5,%6,%7}, {%8,%9}, {%0,%1,%2,%3};"
        : "+f"(c[0]), "+f"(c[1]), "+f"(c[2]), "+f"(c[3])
        : "r"(a[0]), "r"(a[1]), "r"(a[2]), "r"(a[3]), "r"(b[0]), "r"(b[1]));
}

// ---------------------------------------------------------------------------
// GEMM core: D[128x128] = A[128xK] * B[128xK]^T, operands k-minor.
// BK=32, 2-stage cp.async pipeline, XOR-swizzled tiles, 8 warps 2(m)x4(n).
// ---------------------------------------------------------------------------
#define TILE_WORDS (128 * 32)
#define STAGE_WORDS (2 * TILE_WORDS)

extern __shared__ uint32_t smp[];

__device__ __forceinline__ void stage_tile(uint32_t sbase, const float* src,
                                           size_t ld, int tid)
{
    #pragma unroll
    for (int v = 0; v < 4; v++) {
        const int idx = tid + v * 256;
        const int row = idx >> 3;
        const int cg  = idx & 7;
        const uint32_t col4 = (cg * 4) ^ ((row & 7) * 4);
        cp_async16(sbase + (row * 32 + col4) * 4, src + (size_t)row * ld + cg * 4);
    }
}

__device__ __forceinline__ void mma_chunk(const uint32_t* As, const uint32_t* Bs,
                                          float acc[4][4][4],
                                          int wm, int wn, int g, int tig)
{
    const int x4g = 4 * g;
    #pragma unroll
    for (int kk = 0; kk < 4; kk++) {
        const int k  = kk * 8;
        const int c0 = (k + tig) ^ x4g;
        const int c1 = (k + 4 + tig) ^ x4g;
        uint32_t a[4][4], b[4][2];
        #pragma unroll
        for (int mi = 0; mi < 4; mi++) {
            const int r = (wm + mi * 16 + g) * 32;
            a[mi][0] = As[r + c0];
            a[mi][1] = As[r + 256 + c0];
            a[mi][2] = As[r + c1];
            a[mi][3] = As[r + 256 + c1];
        }
        #pragma unroll
        for (int ni = 0; ni < 4; ni++) {
            const int r = (wn + ni * 8 + g) * 32;
            b[ni][0] = Bs[r + c0];
            b[ni][1] = Bs[r + c1];
        }
        #pragma unroll
        for (int mi = 0; mi < 4; mi++)
            #pragma unroll
            for (int ni = 0; ni < 4; ni++)
                mma_tf32(acc[mi][ni], a[mi], b[ni]);
    }
}

__device__ __forceinline__ void gemm_tn(const float* __restrict__ A, size_t lda,
                                        const float* __restrict__ B, size_t ldb,
                                        int nIter, float acc[4][4][4],
                                        int wm, int wn, int g, int tig)
{
    const int tid = threadIdx.x;
    const uint32_t sm0 = s2u(smp);

    stage_tile(sm0, A, lda, tid);
    stage_tile(sm0 + TILE_WORDS * 4, B, ldb, tid);
    CP_COMMIT();

    for (int it = 0; it < nIter; ++it) {
        if (it + 1 < nIter) {
            const uint32_t sb = sm0 + ((it + 1) & 1) * (STAGE_WORDS * 4);
            stage_tile(sb, A + (it + 1) * 32, lda, tid);
            stage_tile(sb + TILE_WORDS * 4, B + (it + 1) * 32, ldb, tid);
            CP_COMMIT();
            CP_WAIT1();
        } else {
            CP_WAIT0();
        }
        __syncthreads();
        const uint32_t* cur = smp + (it & 1) * STAGE_WORDS;
        mma_chunk(cur, cur + TILE_WORDS, acc, wm, wn, g, tig);
        __syncthreads();
    }
}

// ---------------------------------------------------------------------------
// Transpose: xT[b][n][c] = x[b][c][n]
// ---------------------------------------------------------------------------
__global__ __launch_bounds__(256)
void transpose_kernel(const float* __restrict__ x)
{
    __shared__ float t[32][33];
    const int b  = blockIdx.z;
    const int n0 = blockIdx.x * 32;
    const int c0 = blockIdx.y * 32;
    const int tx = threadIdx.x & 31;
    const int ty = threadIdx.x >> 5;

    const float* xb = x + (size_t)b * CCH * HWSZ;
    #pragma unroll
    for (int i = 0; i < 4; i++)
        t[ty + i * 8][tx] = xb[(size_t)(c0 + ty + i * 8) * HWSZ + n0 + tx];
    __syncthreads();
    float* xT = g_xT + (size_t)b * HWSZ * CCH;
    #pragma unroll
    for (int i = 0; i < 4; i++)
        xT[(size_t)(n0 + ty + i * 8) * CCH + c0 + tx] = t[tx][ty + i * 8];
}

// ---------------------------------------------------------------------------
// proj_kp (merged k+p): D[n][r] = sum_c xT[n][c] * W[r][c] + bias[r]
// blockIdx.y in [0,4): y&1 selects r-tile, y>>1 selects (Wk,fkeyT)/(Wp,fprodT)
// ---------------------------------------------------------------------------
__global__ __launch_bounds__(256)
void proj_kp_kernel(const float* __restrict__ Wk, const float* __restrict__ bk,
                    const float* __restrict__ Wp, const float* __restrict__ bp)
{
    const int b  = blockIdx.z;
    const int n0 = blockIdx.x * 128;
    const int which = blockIdx.y >> 1;
    const int r0 = (blockIdx.y & 1) * 128;
    const float* W    = which ? Wp : Wk;
    const float* bias = which ? bp : bk;
    float* dst        = which ? g_fprodT : g_fkeyT;

    const int tid = threadIdx.x;
    const int wid = tid >> 5, lane = tid & 31;
    const int wm = (wid >> 2) * 64, wn = (wid & 3) * 32;
    const int g = lane >> 2, tig = lane & 3;

    float acc[4][4][4] = {};
    gemm_tn(g_xT + (size_t)b * HWSZ * CCH + (size_t)n0 * CCH, CCH,
            W + (size_t)r0 * CCH, CCH, CCH / 32, acc, wm, wn, g, tig);

    #pragma unroll
    for (int ni = 0; ni < 4; ni++) {
        const int col = r0 + wn + ni * 8 + tig * 2;
        const float2 bv = *reinterpret_cast<const float2*>(&bias[col]);
        #pragma unroll
        for (int mi = 0; mi < 4; mi++) {
            const int row = n0 + wm + mi * 16 + g;
            *reinterpret_cast<float2*>(&dst[((size_t)b * HWSZ + row) * RCH + col]) =
                make_float2(acc[mi][ni][0] + bv.x, acc[mi][ni][1] + bv.y);
            *reinterpret_cast<float2*>(&dst[((size_t)b * HWSZ + row + 8) * RCH + col]) =
                make_float2(acc[mi][ni][2] + bv.x, acc[mi][ni][3] + bv.y);
        }
    }
}

// ---------------------------------------------------------------------------
// proj_v: D[c][m] = sum_ci Wv[c][ci] * xT[m][ci] + bias[c] -> fval[b][c][m]
// ---------------------------------------------------------------------------
__global__ __launch_bounds__(256)
void proj_v_kernel(const float* __restrict__ Wv, const float* __restrict__ bias)
{
    const int b  = blockIdx.z;
    const int m0 = blockIdx.x * 128;
    const int c0 = blockIdx.y * 128;
    const int tid = threadIdx.x;
    const int wid = tid >> 5, lane = tid & 31;
    const int wm = (wid >> 2) * 64, wn = (wid & 3) * 32;
    const int g = lane >> 2, tig = lane & 3;

    float acc[4][4][4] = {};
    gemm_tn(Wv + (size_t)c0 * CCH, CCH,
            g_xT + (size_t)b * HWSZ * CCH + (size_t)m0 * CCH, CCH,
            CCH / 32, acc, wm, wn, g, tig);

    #pragma unroll
    for (int mi = 0; mi < 4; mi++) {
        const int row = c0 + wm + mi * 16 + g;
        const float b0 = bias[row], b1 = bias[row + 8];
        #pragma unroll
        for (int ni = 0; ni < 4; ni++) {
            const int col = m0 + wn + ni * 8 + tig * 2;
            *reinterpret_cast<float2*>(&g_fval[((size_t)b * CCH + row) * HWSZ + col]) =
                make_float2(acc[mi][ni][0] + b0, acc[mi][ni][1] + b0);
            *reinterpret_cast<float2*>(&g_fval[((size_t)b * CCH + row + 8) * HWSZ + col]) =
                make_float2(acc[mi][ni][2] + b1, acc[mi][ni][3] + b1);
        }
    }
}

// ---------------------------------------------------------------------------
// energy: writes P = exp(E - SHIFT) and per-CTA row partial sums.
// E[n][m] = sum_r fkeyT[n][r] * fprodT[m][r]
// ---------------------------------------------------------------------------
__global__ __launch_bounds__(256)
void energy_kernel()
{
    const int b  = blockIdx.z;
    const int m0 = blockIdx.x * 128;
    const int n0 = blockIdx.y * 128;
    const int tid = threadIdx.x;
    const int wid = tid >> 5, lane = tid & 31;
    const int wm = (wid >> 2) * 64, wn = (wid & 3) * 32;
    const int g = lane >> 2, tig = lane & 3;

    float acc[4][4][4] = {};
    gemm_tn(g_fkeyT  + ((size_t)b * HWSZ + n0) * RCH, RCH,
            g_fprodT + ((size_t)b * HWSZ + m0) * RCH, RCH,
            RCH / 32, acc, wm, wn, g, tig);

    // exp in place
    #pragma unroll
    for (int mi = 0; mi < 4; mi++)
        #pragma unroll
        for (int ni = 0; ni < 4; ni++)
            #pragma unroll
            for (int q = 0; q < 4; q++)
                acc[mi][ni][q] = __expf(acc[mi][ni][q] - EXP_SHIFT);

    // store P tile
    float* Eb = g_energy + (size_t)b * HWSZ * HWSZ;
    #pragma unroll
    for (int mi = 0; mi < 4; mi++) {
        const int row = n0 + wm + mi * 16 + g;
        #pragma unroll
        for (int ni = 0; ni < 4; ni++) {
            const int col = m0 + wn + ni * 8 + tig * 2;
            *reinterpret_cast<float2*>(&Eb[(size_t)row * HWSZ + col]) =
                make_float2(acc[mi][ni][0], acc[mi][ni][1]);
            *reinterpret_cast<float2*>(&Eb[(size_t)(row + 8) * HWSZ + col]) =
                make_float2(acc[mi][ni][2], acc[mi][ni][3]);
        }
    }

    // per-row partial sums over this CTA's 128 m-columns
    __syncthreads();                                 // pipeline smem now dead
    float* spart = reinterpret_cast<float*>(smp);    // [128][5] scratch
    #pragma unroll
    for (int mi = 0; mi < 4; mi++) {
        float slo = 0.f, shi = 0.f;
        #pragma unroll
        for (int ni = 0; ni < 4; ni++) {
            slo += acc[mi][ni][0] + acc[mi][ni][1];
            shi += acc[mi][ni][2] + acc[mi][ni][3];
        }
        // reduce over tig (lanes g*4 + tig)
        #pragma unroll
        for (int o = 1; o < 4; o <<= 1) {
            slo += __shfl_xor_sync(0xffffffffu, slo, o);
            shi += __shfl_xor_sync(0xffffffffu, shi, o);
        }
        if (tig == 0) {
            spart[(wm + mi * 16 + g) * 5 + (wid & 3)] = slo;
            spart[(wm + mi * 16 + g + 8) * 5 + (wid & 3)] = shi;
        }
    }
    __syncthreads();
    if (tid < 128) {
        const float s = spart[tid * 5 + 0] + spart[tid * 5 + 1] +
                        spart[tid * 5 + 2] + spart[tid * 5 + 3];
        g_epart[((size_t)b * HWSZ + n0 + tid) * 8 + blockIdx.x] = s;
    }
}

// ---------------------------------------------------------------------------
// inv: g_inv[row] = 1 / sum_8 partials
// ---------------------------------------------------------------------------
__global__ __launch_bounds__(1024)
void inv_kernel()
{
    const int row = blockIdx.x * 1024 + threadIdx.x;
    const float* p = &g_epart[(size_t)row * 8];
    float s = 0.f;
    #pragma unroll
    for (int i = 0; i < 8; i++) s += p[i];
    g_inv[row] = 1.0f / s;
}

// ---------------------------------------------------------------------------
// attended: D[c][n] = sum_m fval[c][m] * P[n][m];
// out[c][n] = x[c][n] + param * inv[n] * D[c][n]
// ---------------------------------------------------------------------------
__global__ __launch_bounds__(256)
void attended_kernel(const float* __restrict__ x,
                     const float* __restrict__ param,
                     float* __restrict__ out)
{
    const int b  = blockIdx.z;
    const int n0 = blockIdx.x * 128;
    const int c0 = blockIdx.y * 128;
    const int tid = threadIdx.x;
    const int wid = tid >> 5, lane = tid & 31;
    const int wm = (wid >> 2) * 64, wn = (wid & 3) * 32;
    const int g = lane >> 2, tig = lane & 3;

    float acc[4][4][4] = {};
    gemm_tn(g_fval + ((size_t)b * CCH + c0) * HWSZ, HWSZ,
            g_energy + ((size_t)b * HWSZ + n0) * HWSZ, HWSZ,
            HWSZ / 32, acc, wm, wn, g, tig);

    const float ps = param[0];
    const float* xb = x   + (size_t)b * CCH * HWSZ;
    float*       ob = out + (size_t)b * CCH * HWSZ;
    #pragma unroll
    for (int ni = 0; ni < 4; ni++) {
        const int col = n0 + wn + ni * 8 + tig * 2;
        float2 iv = *reinterpret_cast<const float2*>(&g_inv[(size_t)b * HWSZ + col]);
        const float sx = ps * iv.x, sy = ps * iv.y;
        #pragma unroll
        for (int mi = 0; mi < 4; mi++) {
            const int row = c0 + wm + mi * 16 + g;
            {
                const size_t off = (size_t)row * HWSZ + col;
                float2 xv = *reinterpret_cast<const float2*>(&xb[off]);
                *reinterpret_cast<float2*>(&ob[off]) =
                    make_float2(xv.x + sx * acc[mi][ni][0],
                                xv.y + sy * acc[mi][ni][1]);
            }
            {
                const size_t off = (size_t)(row + 8) * HWSZ + col;
                float2 xv = *reinterpret_cast<const float2*>(&xb[off]);
                *reinterpret_cast<float2*>(&ob[off]) =
                    make_float2(xv.x + sx * acc[mi][ni][2],
                                xv.y + sy * acc[mi][ni][3]);
            }
        }
    }
}

// ---------------------------------------------------------------------------
extern "C" void kernel_launch(void* const* d_in, const int* in_sizes, int n_in,
                              void* d_out, int out_size)
{
    const float* x     = (const float*)d_in[0];
    const float* Wk    = (const float*)d_in[1];
    const float* bk    = (const float*)d_in[2];
    const float* Wp    = (const float*)d_in[3];
    const float* bp    = (const float*)d_in[4];
    const float* Wv    = (const float*)d_in[5];
    const float* bv    = (const float*)d_in[6];
    const float* param = (const float*)d_in[7];
    float* out = (float*)d_out;

    const int DSM = 2 * STAGE_WORDS * 4;   // 64 KB dynamic smem
    cudaFuncSetAttribute(proj_kp_kernel,  cudaFuncAttributeMaxDynamicSharedMemorySize, DSM);
    cudaFuncSetAttribute(proj_v_kernel,   cudaFuncAttributeMaxDynamicSharedMemorySize, DSM);
    cudaFuncSetAttribute(energy_kernel,   cudaFuncAttributeMaxDynamicSharedMemorySize, DSM);
    cudaFuncSetAttribute(attended_kernel, cudaFuncAttributeMaxDynamicSharedMemorySize, DSM);

    transpose_kernel<<<dim3(HWSZ / 32, CCH / 32, BATCH), 256>>>(x);

    proj_kp_kernel<<<dim3(HWSZ / 128, 4, BATCH), 256, DSM>>>(Wk, bk, Wp, bp);
    proj_v_kernel <<<dim3(HWSZ / 128, CCH / 128, BATCH), 256, DSM>>>(Wv, bv);

    energy_kernel<<<dim3(HWSZ / 128, HWSZ / 128, BATCH), 256, DSM>>>();
    inv_kernel   <<<dim3(BATCH * HWSZ / 1024), 1024>>>();

    attended_kernel<<<dim3(HWSZ / 128, CCH / 128, BATCH), 256, DSM>>>(x, param, out);
}